// round 4
// baseline (speedup 1.0000x reference)
#include <cuda_runtime.h>
#include <stdint.h>

#define BB 128
#define TT 1024
#define NN 256
#define FULL 0xffffffffu
#define KMAX 32      // hard cap on candidates per row (global storage)
#define KS   8       // candidates cached in smem
#define PMAX 16      // trans pairs cached in smem per step

// Scratch (device globals; allocation-free per harness rules)
__device__ uint8_t g_cnt [BB * TT];
__device__ uint8_t g_cidx[(size_t)BB * TT * KMAX];
__device__ float   g_cpot[(size_t)BB * TT * KMAX];
__device__ uint8_t g_bpo [(size_t)BB * TT * KMAX];   // bp overflow slots (cnt > KS)
__device__ uint8_t g_tags[BB * TT];

// Order-preserving float <-> u32 (finite floats only).
__device__ __forceinline__ unsigned fkey(float x) {
    unsigned b = __float_as_uint(x);
    return b ^ ((unsigned)((int)b >> 31) | 0x80000000u);
}
__device__ __forceinline__ float finv(unsigned u) {
    return __uint_as_float(u ^ (~(unsigned)((int)u >> 31) | 0x80000000u));
}

// ---------------------------------------------------------------------------
// Phase 1: per-(b,t) candidate extraction, fully parallel.
// S_t (all possible argmax sources / ties / final winners) is contained in
// C_t = { i : pot_t[i] >= max(pot_t) - 0.2 - eps }   (transitions in ±0.05).
// One warp per row; enumeration ascending by state index.
// ---------------------------------------------------------------------------
__global__ __launch_bounds__(256) void cand_kernel(const float* __restrict__ pot)
{
    int row  = (blockIdx.x << 3) + (threadIdx.x >> 5);
    int lane = threadIdx.x & 31;
    const float* r = pot + (size_t)row * NN;

    float a[8];
    #pragma unroll
    for (int k = 0; k < 8; k++) a[k] = __ldcs(&r[(k << 5) + lane]);

    float m = fmaxf(fmaxf(fmaxf(a[0], a[1]), fmaxf(a[2], a[3])),
                    fmaxf(fmaxf(a[4], a[5]), fmaxf(a[6], a[7])));
    m = finv(__reduce_max_sync(FULL, fkey(m)));
    float thr = m - 0.22f;   // 0.1 prune + 0.1 beta spread + 0.02 fp margin

    int base = 0;
    #pragma unroll
    for (int k = 0; k < 8; k++) {
        unsigned mm = __ballot_sync(FULL, a[k] >= thr);
        if (a[k] >= thr) {
            int pos = base + __popc(mm & ((1u << lane) - 1u));
            if (pos < KMAX) {
                g_cidx[(size_t)row * KMAX + pos] = (uint8_t)((k << 5) + lane);
                g_cpot[(size_t)row * KMAX + pos] = a[k];
            }
        }
        base += __popc(mm);
    }
    if (lane == 0) g_cnt[row] = (uint8_t)min(base, KMAX);
}

// ---------------------------------------------------------------------------
// Phase 2: per-batch serial walk over candidates only, everything in SMEM.
// ---------------------------------------------------------------------------
extern __shared__ char smem_raw[];

__global__ __launch_bounds__(256) void walk_kernel(const float* __restrict__ trans,
                                                   const int*   __restrict__ lens)
{
    const int b   = blockIdx.x;
    const int tid = threadIdx.x;
    const int len = lens[b];

    float*   s_tr  = (float*)smem_raw;                  // [TT][PMAX]
    float*   s_pot = s_tr + TT * PMAX;                  // [TT][KS]
    float*   s_a   = s_pot + TT * KS;                   // [2][KMAX] ping-pong
    uint8_t* s_idx = (uint8_t*)(s_a + 2 * KMAX);        // [TT][KS]
    uint8_t* s_bp  = s_idx + TT * KS;                   // [TT][KS]
    uint8_t* s_cnt = s_bp + TT * KS;                    // [TT]
    uint8_t* s_pvf = s_cnt + TT;                        // [TT] pair-overflow flag
    short*   s_tag = (short*)(s_pvf + TT);              // [TT]

    // ---- stage candidate data into smem (parallel) ----
    for (int t = tid; t < len; t += 256) {
        size_t r = (size_t)b * TT + t;
        int c = g_cnt[r];
        s_cnt[t] = (uint8_t)c;
        s_pvf[t] = 0;
        int cs = min(c, KS);
        for (int p = 0; p < cs; p++) {
            s_idx[t * KS + p] = g_cidx[r * KMAX + p];
            s_pot[t * KS + p] = g_cpot[r * KMAX + p];
        }
    }
    __syncthreads();

    // ---- gather needed trans[i,j] pairs (parallel; addresses known a priori) ----
    for (int t = tid + 1; t < len; t += 256) {
        int cp = s_cnt[t - 1], cc = s_cnt[t];
        if (cp <= KS && cc <= KS && cp * cc <= PMAX) {
            int p = 0;
            for (int pi = 0; pi < cp; pi++) {
                int i = s_idx[(t - 1) * KS + pi];
                for (int pj = 0; pj < cc; pj++, p++) {
                    int j = s_idx[t * KS + pj];
                    s_tr[t * PMAX + p] = __ldg(&trans[i * NN + j]);
                }
            }
        } else {
            s_pvf[t] = 1;
        }
    }
    __syncthreads();

    // ---- serial recurrence + backtrack (single thread; smem-resident) ----
    if (tid == 0) {
        int cp = s_cnt[0];
        for (int p = 0; p < cp; p++)
            s_a[p] = (p < KS) ? s_pot[p] : g_cpot[(size_t)b * TT * KMAX + p];
        int   cur = 0;
        float a0  = s_a[0];
        int   i0  = s_idx[0];               // valid whenever cp == 1

        // register prefetch of next step's hot operands
        int   cntN = 0; float trN = 0.f, potN = 0.f; int idxN = 0;
        if (len > 1) {
            cntN = s_cnt[1]; trN = s_tr[PMAX]; potN = s_pot[KS]; idxN = s_idx[KS];
        }

        for (int t = 1; t < len; t++) {
            int   cc   = cntN;
            float tr0  = trN, pot0 = potN;
            int   j0   = idxN;
            if (t + 1 < len) {
                cntN = s_cnt[t + 1];
                trN  = s_tr[(t + 1) * PMAX];
                potN = s_pot[(t + 1) * KS];
                idxN = s_idx[(t + 1) * KS];
            }

            if ((cp == 1) & (cc == 1)) {        // fast path: pure scalar chain
                a0 = a0 + tr0 + pot0;
                s_bp[t * KS] = (uint8_t)i0;
                i0 = j0;
                continue;
            }

            // general path
            float* ap = s_a + cur * KMAX;
            float* an = s_a + (cur ^ 1) * KMAX;
            if (cp == 1) ap[0] = a0;
            bool povf = s_pvf[t] != 0;

            for (int pj = 0; pj < cc; pj++) {
                int j = (pj < KS) ? s_idx[t * KS + pj]
                                  : g_cidx[((size_t)b * TT + t) * KMAX + pj];
                float best = -3.4e38f;
                int   bpi  = 0;
                for (int pi = 0; pi < cp; pi++) {
                    float tr;
                    if (!povf) {
                        tr = s_tr[t * PMAX + pi * cc + pj];
                    } else {
                        int ii = (pi < KS) ? s_idx[(t - 1) * KS + pi]
                                           : g_cidx[((size_t)b * TT + t - 1) * KMAX + pi];
                        tr = __ldg(&trans[ii * NN + j]);
                    }
                    float v = ap[pi] + tr;
                    if (v > best) { best = v; bpi = pi; }  // ascending pi => first-max
                }
                int iidx = (bpi < KS) ? s_idx[(t - 1) * KS + bpi]
                                      : g_cidx[((size_t)b * TT + t - 1) * KMAX + bpi];
                float pv = (pj < KS) ? s_pot[t * KS + pj]
                                     : g_cpot[((size_t)b * TT + t) * KMAX + pj];
                an[pj] = best + pv;
                if (pj < KS) s_bp[t * KS + pj] = (uint8_t)iidx;
                else         g_bpo[((size_t)b * TT + t) * KMAX + pj] = (uint8_t)iidx;
            }
            cur ^= 1;
            cp = cc;
            if (cc == 1) { a0 = s_a[cur * KMAX]; i0 = s_idx[t * KS]; }
        }

        // final argmax over candidates of alpha_{len-1}
        int btag;
        if (cp == 1) {
            btag = i0;
        } else {
            float* ap = s_a + cur * KMAX;
            float bv = ap[0];
            int   bp_ = 0;
            for (int p = 1; p < cp; p++)
                if (ap[p] > bv) { bv = ap[p]; bp_ = p; }   // strict > = first occurrence
            btag = (bp_ < KS) ? s_idx[(len - 1) * KS + bp_]
                              : g_cidx[((size_t)b * TT + len - 1) * KMAX + bp_];
        }

        // backtrack (smem-resident)
        int tag = btag;
        s_tag[len - 1] = (short)tag;
        for (int t = len - 1; t >= 1; t--) {
            int cc = s_cnt[t];
            int prev;
            if (cc == 1) {
                prev = s_bp[t * KS];
            } else {
                int p = 0;
                for (;;) {
                    int j = (p < KS) ? s_idx[t * KS + p]
                                     : g_cidx[((size_t)b * TT + t) * KMAX + p];
                    if (j == tag) break;
                    p++;
                }
                prev = (p < KS) ? s_bp[t * KS + p]
                                : g_bpo[((size_t)b * TT + t) * KMAX + p];
            }
            tag = prev;
            s_tag[t - 1] = (short)tag;
        }
    }
    __syncthreads();

    for (int t = tid; t < TT; t += 256)
        g_tags[b * TT + t] = (t < len) ? (uint8_t)s_tag[t] : (uint8_t)0;
}

// ---------------------------------------------------------------------------
// Phase 3: one-hot write, float4 streaming stores.
// ---------------------------------------------------------------------------
__global__ __launch_bounds__(256) void onehot_kernel(float* __restrict__ out)
{
    int k   = blockIdx.x * 256 + threadIdx.x;
    int row = k >> 6;
    int j0  = (k & 63) << 2;
    int tg  = g_tags[row];
    float4 v;
    v.x = (j0     == tg) ? 1.f : 0.f;
    v.y = (j0 + 1 == tg) ? 1.f : 0.f;
    v.z = (j0 + 2 == tg) ? 1.f : 0.f;
    v.w = (j0 + 3 == tg) ? 1.f : 0.f;
    ((float4*)out)[k] = v;
}

extern "C" void kernel_launch(void* const* d_in, const int* in_sizes, int n_in,
                              void* d_out, int out_size)
{
    const float* pot   = (const float*)d_in[0];   // [B, T, N] fp32
    const float* trans = (const float*)d_in[1];   // [N, N]   fp32
    const int*   lens  = (const int*)d_in[2];     // [B]      int32
    float*       out   = (float*)d_out;           // [B, T, N] fp32 one-hot

    // dyn smem: tr 64KB + pot 32KB + a 256B + idx 8KB + bp 8KB + cnt 1KB
    //           + pvf 1KB + tag 2KB  ~= 116.3KB
    const int SMEM_BYTES = TT * PMAX * 4 + TT * KS * 4 + 2 * KMAX * 4
                         + TT * KS + TT * KS + TT + TT + TT * 2;
    static int attr_set = 0;
    cudaFuncSetAttribute(walk_kernel, cudaFuncAttributeMaxDynamicSharedMemorySize,
                         SMEM_BYTES);
    (void)attr_set;

    cand_kernel<<<(BB * TT) / 8, 256>>>(pot);
    walk_kernel<<<BB, 256, SMEM_BYTES>>>(trans, lens);
    onehot_kernel<<<(BB * TT * NN / 4) / 256, 256>>>(out);
}

// round 5
// speedup vs baseline: 1.5773x; 1.5773x over previous
#include <cuda_runtime.h>
#include <stdint.h>

#define BB 128
#define TT 1024
#define NN 256
#define FULL 0xffffffffu
#define KMAX 32      // hard cap on candidates per row (global storage)
#define KC   12      // candidates cached in smem (P(cnt>12) ~ 1e-10 per row)
#define PMAX 16      // trans pairs cached in smem per step

// Scratch (device globals; allocation-free per harness rules)
__device__ uint8_t g_cnt [BB * TT];
__device__ uint8_t g_cidx[(size_t)BB * TT * KMAX];
__device__ float   g_cpot[(size_t)BB * TT * KMAX];
__device__ uint8_t g_bpo [(size_t)BB * TT * KMAX];   // bp overflow (slot >= KC)
__device__ uint8_t g_tags[BB * TT];

__device__ __forceinline__ unsigned fkey(float x) {
    unsigned b = __float_as_uint(x);
    return b ^ ((unsigned)((int)b >> 31) | 0x80000000u);
}
__device__ __forceinline__ float finv(unsigned u) {
    return __uint_as_float(u ^ (~(unsigned)((int)u >> 31) | 0x80000000u));
}

// ---------------------------------------------------------------------------
// Phase 1: candidate extraction (near HBM roofline already).
// All possible argmax sources / ties / winners at row t lie in
// C_t = { i : pot_t[i] >= max(pot_t) - 0.22 }  (transitions span ±0.05).
// ---------------------------------------------------------------------------
__global__ __launch_bounds__(256) void cand_kernel(const float* __restrict__ pot)
{
    int row  = (blockIdx.x << 3) + (threadIdx.x >> 5);
    int lane = threadIdx.x & 31;
    const float* r = pot + (size_t)row * NN;

    float a[8];
    #pragma unroll
    for (int k = 0; k < 8; k++) a[k] = __ldcs(&r[(k << 5) + lane]);

    float m = fmaxf(fmaxf(fmaxf(a[0], a[1]), fmaxf(a[2], a[3])),
                    fmaxf(fmaxf(a[4], a[5]), fmaxf(a[6], a[7])));
    m = finv(__reduce_max_sync(FULL, fkey(m)));
    float thr = m - 0.22f;

    int base = 0;
    #pragma unroll
    for (int k = 0; k < 8; k++) {
        unsigned mm = __ballot_sync(FULL, a[k] >= thr);
        if (a[k] >= thr) {
            int pos = base + __popc(mm & ((1u << lane) - 1u));
            if (pos < KMAX) {
                g_cidx[(size_t)row * KMAX + pos] = (uint8_t)((k << 5) + lane);
                g_cpot[(size_t)row * KMAX + pos] = a[k];
            }
        }
        base += __popc(mm);
    }
    if (lane == 0) g_cnt[row] = (uint8_t)min(base, KMAX);
}

// ---------------------------------------------------------------------------
// Phase 2: per-batch walk. Warp-collective value chain + parallel anchor
// backtrack. One block per batch.
// ---------------------------------------------------------------------------
extern __shared__ char smem_raw[];

__global__ __launch_bounds__(256) void walk_kernel(const float* __restrict__ trans,
                                                   const int*   __restrict__ lens)
{
    const int b   = blockIdx.x;
    const int tid = threadIdx.x;
    const int len = lens[b];
    const size_t rowbase = (size_t)b * TT;

    int*     s_final = (int*)smem_raw;                  // 4B
    float*   s_tr  = (float*)(smem_raw + 4);            // [TT][PMAX]
    float*   s_pot = s_tr + TT * PMAX;                  // [TT][KC]
    uint8_t* s_idx = (uint8_t*)(s_pot + TT * KC);       // [TT][KC]
    uint8_t* s_bp  = s_idx + TT * KC;                   // [TT][KC]
    uint8_t* s_cnt = s_bp + TT * KC;                    // [TT]
    uint8_t* s_pok = s_cnt + TT;                        // [TT]
    short*   s_tag = (short*)(s_pok + TT);              // [TT]

    // ---- stage candidate lists (parallel) ----
    for (int t = tid; t < len; t += 256) {
        size_t r = rowbase + t;
        int c = g_cnt[r];
        s_cnt[t] = (uint8_t)c;
        int cs = min(c, KC);
        for (int p = 0; p < cs; p++) {
            s_idx[t * KC + p] = g_cidx[r * KMAX + p];
            s_pot[t * KC + p] = g_cpot[r * KMAX + p];
        }
    }
    __syncthreads();

    // ---- gather trans[i,j] pairs (parallel; addresses known a priori) ----
    for (int t = tid + 1; t < len; t += 256) {
        int cp = s_cnt[t - 1], cc = s_cnt[t];
        bool ok = (cp <= KC) && (cc <= KC) && (cp * cc <= PMAX);
        s_pok[t] = ok ? 1 : 0;
        if (ok) {
            for (int pi = 0; pi < cp; pi++) {
                int i = s_idx[(t - 1) * KC + pi];
                for (int pj = 0; pj < cc; pj++) {
                    int j = s_idx[t * KC + pj];
                    s_tr[t * PMAX + pi * cc + pj] = __ldg(&trans[i * NN + j]);
                }
            }
        }
    }
    __syncthreads();

    // ---- warp-collective value chain (warp 0, lane = candidate slot) ----
    if (tid < 32) {
        const int lane = tid;
        int cp = s_cnt[0];
        float a;
        if (lane < KC)      a = s_pot[lane];
        else if (lane < cp) a = g_cpot[rowbase * KMAX + lane];
        else                a = -3.4e38f;

        for (int t = 1; t < len; t++) {
            const int  cc  = s_cnt[t];
            const bool pok = s_pok[t] != 0;

            float pj = 0.f; int myidx = 0;
            if (lane < KC)      { pj = s_pot[t * KC + lane];
                                  myidx = s_idx[t * KC + lane]; }
            else if (lane < cc) { pj = g_cpot[(rowbase + t) * KMAX + lane];
                                  myidx = g_cidx[(rowbase + t) * KMAX + lane]; }

            float best = -3.4e38f;
            int   bii  = 0;
            for (int i = 0; i < cp; i++) {            // warp-uniform trip count
                float ai = __shfl_sync(FULL, a, i);
                int   ii = (i < KC) ? (int)s_idx[(t - 1) * KC + i]
                                    : (int)g_cidx[(rowbase + t - 1) * KMAX + i];
                float tr;
                if (pok)
                    tr = s_tr[t * PMAX + min(i * cc + lane, PMAX - 1)];
                else
                    tr = (lane < cc) ? __ldg(&trans[ii * NN + myidx]) : 0.f;
                float v = ai + tr;                     // exact ref arithmetic
                if (v > best) { best = v; bii = ii; }  // ascending => first-max
            }
            a = best + pj;

            if (lane < cc) {
                if (lane < KC) s_bp[t * KC + lane] = (uint8_t)bii;
                else           g_bpo[(rowbase + t) * KMAX + lane] = (uint8_t)bii;
            }
            cp = cc;
        }

        // final argmax over candidates (slots ascending = states ascending)
        float v  = (lane < cp) ? a : -3.4e38f;
        int   id = lane;
        #pragma unroll
        for (int off = 16; off; off >>= 1) {
            float ov  = __shfl_xor_sync(FULL, v, off);
            int   oid = __shfl_xor_sync(FULL, id, off);
            if (ov > v || (ov == v && oid < id)) { v = ov; id = oid; }
        }
        if (lane == 0)
            *s_final = (id < KC) ? (int)s_idx[(len - 1) * KC + id]
                                 : (int)g_cidx[(rowbase + len - 1) * KMAX + id];
    }
    __syncthreads();

    // ---- parallel anchor backtrack ----
    // Any row with cnt==1 has a forced tag (its single candidate). Each
    // anchor resolves the run of multi-candidate rows directly below it.
    for (int r = tid; r < len; r += 256) {
        bool anchor = (s_cnt[r] == 1) || (r == len - 1);
        if (!anchor) continue;
        int tag = (r == len - 1) ? *s_final : (int)s_idx[r * KC];
        s_tag[r] = (short)tag;
        int t = r;
        while (t >= 1 && s_cnt[t - 1] != 1) {
            int cc = s_cnt[t];
            int p = 0;
            if (cc > 1) {
                for (;;) {
                    int j = (p < KC) ? (int)s_idx[t * KC + p]
                                     : (int)g_cidx[(rowbase + t) * KMAX + p];
                    if (j == tag) break;
                    p++;
                }
            }
            tag = (p < KC) ? (int)s_bp[t * KC + p]
                           : (int)g_bpo[(rowbase + t) * KMAX + p];
            t--;
            s_tag[t] = (short)tag;
        }
    }
    __syncthreads();

    for (int t = tid; t < TT; t += 256)
        g_tags[rowbase + t] = (t < len) ? (uint8_t)s_tag[t] : (uint8_t)0;
}

// ---------------------------------------------------------------------------
// Phase 3: one-hot write, float4 streaming stores.
// ---------------------------------------------------------------------------
__global__ __launch_bounds__(256) void onehot_kernel(float* __restrict__ out)
{
    int k   = blockIdx.x * 256 + threadIdx.x;
    int row = k >> 6;
    int j0  = (k & 63) << 2;
    int tg  = g_tags[row];
    float4 v;
    v.x = (j0     == tg) ? 1.f : 0.f;
    v.y = (j0 + 1 == tg) ? 1.f : 0.f;
    v.z = (j0 + 2 == tg) ? 1.f : 0.f;
    v.w = (j0 + 3 == tg) ? 1.f : 0.f;
    ((float4*)out)[k] = v;
}

extern "C" void kernel_launch(void* const* d_in, const int* in_sizes, int n_in,
                              void* d_out, int out_size)
{
    const float* pot   = (const float*)d_in[0];   // [B, T, N] fp32
    const float* trans = (const float*)d_in[1];   // [N, N]   fp32
    const int*   lens  = (const int*)d_in[2];     // [B]      int32
    float*       out   = (float*)d_out;           // [B, T, N] fp32 one-hot

    const int SMEM_BYTES = 4 + TT * PMAX * 4 + TT * KC * 4
                         + TT * KC + TT * KC + TT + TT + TT * 2;   // ~140KB
    cudaFuncSetAttribute(walk_kernel, cudaFuncAttributeMaxDynamicSharedMemorySize,
                         SMEM_BYTES);

    cand_kernel<<<(BB * TT) / 8, 256>>>(pot);
    walk_kernel<<<BB, 256, SMEM_BYTES>>>(trans, lens);
    onehot_kernel<<<(BB * TT * NN / 4) / 256, 256>>>(out);
}

// round 6
// speedup vs baseline: 2.8312x; 1.7950x over previous
#include <cuda_runtime.h>
#include <stdint.h>

#define BB 128
#define TT 1024
#define NN 256
#define FULL 0xffffffffu
#define KMAX 32      // hard cap on candidates (global storage)
#define KF   4       // fast-path candidate cap (P(cnt>4) ~ 5e-4 per row)
#define NEGF (-3.4e38f)

// Scratch (device globals; allocation-free per harness rules)
__device__ uint8_t g_cnt [BB * TT];
__device__ uint8_t g_cidx[(size_t)BB * TT * KMAX];
__device__ float   g_cpot[(size_t)BB * TT * KMAX];
__device__ uint8_t g_bpo [(size_t)BB * TT * KMAX];   // bp overflow (slot >= KF)

__device__ __forceinline__ unsigned fkey(float x) {
    unsigned b = __float_as_uint(x);
    return b ^ ((unsigned)((int)b >> 31) | 0x80000000u);
}
__device__ __forceinline__ float finv(unsigned u) {
    return __uint_as_float(u ^ (~(unsigned)((int)u >> 31) | 0x80000000u));
}

// ---------------------------------------------------------------------------
// Phase 1: candidate extraction (66% of HBM roofline).
// All possible argmax sources / ties / winners at row t lie in
// C_t = { i : pot_t[i] >= max(pot_t) - 0.22 }   (transitions span ±0.05).
// Enumeration ascending by state index.
// ---------------------------------------------------------------------------
__global__ __launch_bounds__(256) void cand_kernel(const float* __restrict__ pot)
{
    int row  = (blockIdx.x << 3) + (threadIdx.x >> 5);
    int lane = threadIdx.x & 31;
    const float* r = pot + (size_t)row * NN;

    float a[8];
    #pragma unroll
    for (int k = 0; k < 8; k++) a[k] = __ldcs(&r[(k << 5) + lane]);

    float m = fmaxf(fmaxf(fmaxf(a[0], a[1]), fmaxf(a[2], a[3])),
                    fmaxf(fmaxf(a[4], a[5]), fmaxf(a[6], a[7])));
    m = finv(__reduce_max_sync(FULL, fkey(m)));
    float thr = m - 0.22f;

    int base = 0;
    #pragma unroll
    for (int k = 0; k < 8; k++) {
        unsigned mm = __ballot_sync(FULL, a[k] >= thr);
        if (a[k] >= thr) {
            int pos = base + __popc(mm & ((1u << lane) - 1u));
            if (pos < KMAX) {
                g_cidx[(size_t)row * KMAX + pos] = (uint8_t)((k << 5) + lane);
                g_cpot[(size_t)row * KMAX + pos] = a[k];
            }
        }
        base += __popc(mm);
    }
    if (lane == 0) g_cnt[row] = (uint8_t)min(base, KMAX);
}

// ---------------------------------------------------------------------------
// Phase 2: walk + backtrack + fused one-hot write. One block per batch.
// Chain = replicated-register K=4 max-plus, branch-light, operands
// software-pipelined one step ahead from SMEM.
// ---------------------------------------------------------------------------
extern __shared__ char smem_raw[];

__global__ __launch_bounds__(256) void walk_kernel(const float* __restrict__ trans,
                                                   const int*   __restrict__ lens,
                                                   float*       __restrict__ out)
{
    const int b   = blockIdx.x;
    const int tid = threadIdx.x;
    const int len = lens[b];
    const size_t rowbase = (size_t)b * TT;

    float*   s_tr   = (float*)smem_raw;              // [TT][16]  64KB
    float*   s_pot  = s_tr + TT * 16;                // [TT][4]   16KB
    float*   s_aext = s_pot + TT * 4;                // [2][KMAX] 256B
    short*   s_tag  = (short*)(s_aext + 2 * KMAX);   // [TT]      2KB
    int*     s_final= (int*)(s_tag + TT);            // 4B
    uint8_t* s_idx  = (uint8_t*)(s_final + 1);       // [TT][4]   4KB
    uint8_t* s_bp   = s_idx + TT * 4;                // [TT][4]   4KB
    uint8_t* s_meta = s_bp + TT * 4;                 // [TT]      1KB

    // ---- stage candidate lists (parallel) ----
    for (int t = tid; t < len; t += 256) {
        size_t r = rowbase + t;
        int c = g_cnt[r];
        s_meta[t] = (uint8_t)c;
        int cs = min(c, KF);
        for (int p = 0; p < cs; p++) {
            s_idx[t * 4 + p] = g_cidx[r * KMAX + p];
            s_pot[t * 4 + p] = g_cpot[r * KMAX + p];
        }
    }
    __syncthreads();

    // ---- gather 4x4 trans blocks; set fast-path bit (parallel) ----
    for (int t = tid + 1; t < len; t += 256) {
        int cp_ = s_meta[t - 1] & 63, cc_ = s_meta[t] & 63;
        if (cp_ <= KF && cc_ <= KF) {
            #pragma unroll
            for (int pi = 0; pi < 4; pi++) {
                float v0 = 0.f, v1 = 0.f, v2 = 0.f, v3 = 0.f;
                if (pi < cp_) {
                    const float* trow = trans + (int)s_idx[(t - 1) * 4 + pi] * NN;
                    v0 = __ldg(&trow[s_idx[t * 4 + 0]]);
                    if (cc_ > 1) v1 = __ldg(&trow[s_idx[t * 4 + 1]]);
                    if (cc_ > 2) v2 = __ldg(&trow[s_idx[t * 4 + 2]]);
                    if (cc_ > 3) v3 = __ldg(&trow[s_idx[t * 4 + 3]]);
                }
                *(float4*)&s_tr[t * 16 + pi * 4] = make_float4(v0, v1, v2, v3);
            }
            s_meta[t] = (uint8_t)(cc_ | 0x80);
        }
    }
    __syncthreads();

    // ---- recurrence (warp 0; all lanes redundant, zero shuffles) ----
    if (tid < 32) {
        const int lane = tid;
        int cp = s_meta[0] & 63;
        float4 p0 = *(float4*)&s_pot[0];
        float a0 = p0.x;
        float a1 = (cp > 1) ? p0.y : NEGF;
        float a2 = (cp > 2) ? p0.z : NEGF;
        float a3 = (cp > 3) ? p0.w : NEGF;
        uint32_t idxp = *(uint32_t*)&s_idx[0];
        int curext = 0;
        if (cp > KF) {
            if (lane < cp) s_aext[lane] = g_cpot[rowbase * KMAX + lane];
            __syncwarp();
        }

        // one-step-ahead operand buffer
        uint32_t meN = 0, ixN = 0;
        float4 ptN = {0,0,0,0}, q0N = {0,0,0,0}, q1N = {0,0,0,0},
               q2N = {0,0,0,0}, q3N = {0,0,0,0};
        if (len > 1) {
            meN = s_meta[1]; ixN = *(uint32_t*)&s_idx[4];
            ptN = *(float4*)&s_pot[4];
            const float4* tr4 = (const float4*)&s_tr[16];
            q0N = tr4[0]; q1N = tr4[1]; q2N = tr4[2]; q3N = tr4[3];
        }

        for (int t = 1; t < len; t++) {
            uint32_t me = meN, ixc = ixN;
            float4 pt = ptN, r0 = q0N, r1 = q1N, r2 = q2N, r3 = q3N;
            {   // prefetch t+1 (clamped)
                int tn = (t + 1 < len) ? (t + 1) : (len - 1);
                meN = s_meta[tn]; ixN = *(uint32_t*)&s_idx[tn * 4];
                ptN = *(float4*)&s_pot[tn * 4];
                const float4* tr4 = (const float4*)&s_tr[tn * 16];
                q0N = tr4[0]; q1N = tr4[1]; q2N = tr4[2]; q3N = tr4[3];
            }
            int cc = me & 63;

            if (me & 0x80) {   // fast: cp<=4 && cc<=4, trans block staged
                if (cp == 1 && cc == 1) {
                    a0 = (a0 + r0.x) + pt.x;
                    *(uint32_t*)&s_bp[t * 4] = idxp & 0xffu;
                    a1 = a2 = a3 = NEGF;
                } else {
                    float n0, n1, n2, n3; int s0, s1, s2, s3;
                    { float bsv = a0 + r0.x; int bi = 0; float v;
                      v = a1 + r1.x; if (v > bsv) { bsv = v; bi = 1; }
                      v = a2 + r2.x; if (v > bsv) { bsv = v; bi = 2; }
                      v = a3 + r3.x; if (v > bsv) { bsv = v; bi = 3; }
                      n0 = bsv + pt.x; s0 = bi; }
                    { float bsv = a0 + r0.y; int bi = 0; float v;
                      v = a1 + r1.y; if (v > bsv) { bsv = v; bi = 1; }
                      v = a2 + r2.y; if (v > bsv) { bsv = v; bi = 2; }
                      v = a3 + r3.y; if (v > bsv) { bsv = v; bi = 3; }
                      n1 = bsv + pt.y; s1 = bi; }
                    { float bsv = a0 + r0.z; int bi = 0; float v;
                      v = a1 + r1.z; if (v > bsv) { bsv = v; bi = 1; }
                      v = a2 + r2.z; if (v > bsv) { bsv = v; bi = 2; }
                      v = a3 + r3.z; if (v > bsv) { bsv = v; bi = 3; }
                      n2 = bsv + pt.z; s2 = bi; }
                    { float bsv = a0 + r0.w; int bi = 0; float v;
                      v = a1 + r1.w; if (v > bsv) { bsv = v; bi = 1; }
                      v = a2 + r2.w; if (v > bsv) { bsv = v; bi = 2; }
                      v = a3 + r3.w; if (v > bsv) { bsv = v; bi = 3; }
                      n3 = bsv + pt.w; s3 = bi; }
                    uint32_t sel = (uint32_t)s0 | ((uint32_t)s1 << 4)
                                 | ((uint32_t)s2 << 8) | ((uint32_t)s3 << 12);
                    *(uint32_t*)&s_bp[t * 4] = __byte_perm(idxp, 0, sel);
                    a0 = n0;
                    a1 = (cc > 1) ? n1 : NEGF;
                    a2 = (cc > 2) ? n2 : NEGF;
                    a3 = (cc > 3) ? n3 : NEGF;
                }
            } else {           // slow: cnt > 4 on either side (~5e-4 of steps)
                float pj = 0.f; int myidx = 0;
                if (lane < cc) {
                    if (lane < KF) { pj = s_pot[t * 4 + lane];
                                     myidx = s_idx[t * 4 + lane]; }
                    else           { pj = g_cpot[(rowbase + t) * KMAX + lane];
                                     myidx = g_cidx[(rowbase + t) * KMAX + lane]; }
                }
                float bsv = NEGF; int bii = 0;
                for (int i = 0; i < cp; i++) {
                    float ai;
                    if (cp <= KF)
                        ai = (i == 0) ? a0 : (i == 1) ? a1 : (i == 2) ? a2 : a3;
                    else
                        ai = s_aext[curext * KMAX + i];
                    int ii = (i < KF) ? (int)((idxp >> (i * 8)) & 0xff)
                                      : (int)g_cidx[(rowbase + t - 1) * KMAX + i];
                    float tr = (lane < cc) ? __ldg(&trans[ii * NN + myidx]) : 0.f;
                    float v = ai + tr;
                    if (v > bsv) { bsv = v; bii = ii; }   // ascending i = first-max
                }
                if (lane < cc) {
                    s_aext[(curext ^ 1) * KMAX + lane] = bsv + pj;
                    if (lane < KF) s_bp[t * 4 + lane] = (uint8_t)bii;
                    else g_bpo[(rowbase + t) * KMAX + lane] = (uint8_t)bii;
                }
                __syncwarp();
                curext ^= 1;
                a0 = s_aext[curext * KMAX + 0];
                a1 = (cc > 1) ? s_aext[curext * KMAX + 1] : NEGF;
                a2 = (cc > 2) ? s_aext[curext * KMAX + 2] : NEGF;
                a3 = (cc > 3) ? s_aext[curext * KMAX + 3] : NEGF;
            }
            idxp = ixc;
            cp = cc;
        }

        // ---- final argmax over last row's candidates ----
        int btag;
        if (cp <= KF) {
            float bv = a0; int bs = 0;
            if (a1 > bv) { bv = a1; bs = 1; }
            if (a2 > bv) { bv = a2; bs = 2; }
            if (a3 > bv) { bv = a3; bs = 3; }
            btag = (int)((idxp >> (bs * 8)) & 0xff);
        } else {
            float bv = NEGF; btag = 0;
            for (int p = 0; p < cp; p++) {
                float v = s_aext[curext * KMAX + p];
                if (v > bv) {
                    bv = v;
                    btag = (p < KF) ? (int)((idxp >> (p * 8)) & 0xff)
                                    : (int)g_cidx[(rowbase + len - 1) * KMAX + p];
                }
            }
        }
        if (lane == 0) *s_final = btag;
    }
    __syncthreads();

    // ---- parallel anchor backtrack (singleton rows force the path) ----
    for (int r = tid; r < len; r += 256) {
        int cr = s_meta[r] & 63;
        bool anchor = (cr == 1) || (r == len - 1);
        if (!anchor) continue;
        int tag = (r == len - 1) ? *s_final : (int)s_idx[r * 4];
        s_tag[r] = (short)tag;
        int t = r;
        while (t >= 1 && (s_meta[t - 1] & 63) != 1) {
            int cc = s_meta[t] & 63;
            int p = 0;
            if (cc > 1) {
                for (;;) {
                    int j = (p < KF) ? (int)s_idx[t * 4 + p]
                                     : (int)g_cidx[(rowbase + t) * KMAX + p];
                    if (j == tag) break;
                    p++;
                }
            }
            tag = (p < KF) ? (int)s_bp[t * 4 + p]
                           : (int)g_bpo[(rowbase + t) * KMAX + p];
            t--;
            s_tag[t] = (short)tag;
        }
    }
    __syncthreads();

    // ---- fused one-hot write: this batch's 1MB, float4 stores ----
    float4* outb = (float4*)(out + (size_t)b * TT * NN);
    for (int k = tid; k < TT * (NN / 4); k += 256) {
        int t  = k >> 6;
        int j0 = (k & 63) << 2;
        int tg = (t < len) ? (int)s_tag[t] : 0;
        float4 v;
        v.x = (j0     == tg) ? 1.f : 0.f;
        v.y = (j0 + 1 == tg) ? 1.f : 0.f;
        v.z = (j0 + 2 == tg) ? 1.f : 0.f;
        v.w = (j0 + 3 == tg) ? 1.f : 0.f;
        outb[k] = v;
    }
}

extern "C" void kernel_launch(void* const* d_in, const int* in_sizes, int n_in,
                              void* d_out, int out_size)
{
    const float* pot   = (const float*)d_in[0];   // [B, T, N] fp32
    const float* trans = (const float*)d_in[1];   // [N, N]   fp32
    const int*   lens  = (const int*)d_in[2];     // [B]      int32
    float*       out   = (float*)d_out;           // [B, T, N] fp32 one-hot

    const int SMEM_BYTES = TT * 16 * 4 + TT * 4 * 4 + 2 * KMAX * 4
                         + TT * 2 + 4 + TT * 4 + TT * 4 + TT;   // 93444B
    cudaFuncSetAttribute(walk_kernel, cudaFuncAttributeMaxDynamicSharedMemorySize,
                         SMEM_BYTES);

    cand_kernel<<<(BB * TT) / 8, 256>>>(pot);
    walk_kernel<<<BB, 256, SMEM_BYTES>>>(trans, lens, out);
}

// round 8
// speedup vs baseline: 3.0978x; 1.0942x over previous
#include <cuda_runtime.h>
#include <stdint.h>

#define BB 128
#define TT 1024
#define NN 256
#define FULL 0xffffffffu
#define KMAX 32      // hard cap on candidates (global storage)
#define KF   4       // fast-path candidate cap (P(cnt>4) ~ 3-6% per row)
#define REC  28      // floats per record (112B): [0:16) trans, [16:20) pot,
                     // [20] idx(packed u8x4), [21] cnt|0x80-fastflag, [24:28) alphas
#define NEGF (-3.4e38f)

// Scratch (device globals; allocation-free per harness rules)
__device__ uint8_t g_cnt [BB * TT];
__device__ uint8_t g_cidx[(size_t)BB * TT * KMAX];
__device__ float   g_cpot[(size_t)BB * TT * KMAX];
__device__ uint8_t g_bpo [(size_t)BB * TT * KMAX];   // slow-step bp, slot >= KF

__device__ __forceinline__ unsigned fkey(float x) {
    unsigned b = __float_as_uint(x);
    return b ^ ((unsigned)((int)b >> 31) | 0x80000000u);
}
__device__ __forceinline__ float finv(unsigned u) {
    return __uint_as_float(u ^ (~(unsigned)((int)u >> 31) | 0x80000000u));
}

// ---------------------------------------------------------------------------
// Phase 1: candidate extraction (66% of HBM roofline).
// All possible argmax sources / ties / winners at row t lie in
// C_t = { i : pot_t[i] >= max(pot_t) - 0.22 }   (transitions span ±0.05).
// Candidates emitted ascending by state index.
// ---------------------------------------------------------------------------
__global__ __launch_bounds__(256) void cand_kernel(const float* __restrict__ pot)
{
    int row  = (blockIdx.x << 3) + (threadIdx.x >> 5);
    int lane = threadIdx.x & 31;
    const float* r = pot + (size_t)row * NN;

    float a[8];
    #pragma unroll
    for (int k = 0; k < 8; k++) a[k] = __ldcs(&r[(k << 5) + lane]);

    float m = fmaxf(fmaxf(fmaxf(a[0], a[1]), fmaxf(a[2], a[3])),
                    fmaxf(fmaxf(a[4], a[5]), fmaxf(a[6], a[7])));
    m = finv(__reduce_max_sync(FULL, fkey(m)));
    float thr = m - 0.22f;

    int base = 0;
    #pragma unroll
    for (int k = 0; k < 8; k++) {
        unsigned mm = __ballot_sync(FULL, a[k] >= thr);
        if (a[k] >= thr) {
            int pos = base + __popc(mm & ((1u << lane) - 1u));
            if (pos < KMAX) {
                g_cidx[(size_t)row * KMAX + pos] = (uint8_t)((k << 5) + lane);
                g_cpot[(size_t)row * KMAX + pos] = a[k];
            }
        }
        base += __popc(mm);
    }
    if (lane == 0) g_cnt[row] = (uint8_t)min(base, KMAX);
}

// ---------------------------------------------------------------------------
// Phase 2: walk + backtrack + fused one-hot write. One block per batch.
// Chain = value-only branch-per-step 4x4 max-plus (fmax tree); backpointers
// for fast steps recomputed at backtrack time from stored alphas.
// ---------------------------------------------------------------------------
extern __shared__ char smem_raw[];

__global__ __launch_bounds__(256) void walk_kernel(const float* __restrict__ trans,
                                                   const int*   __restrict__ lens,
                                                   float*       __restrict__ out)
{
    const int b   = blockIdx.x;
    const int tid = threadIdx.x;
    const int len = lens[b];
    const size_t rowbase = (size_t)b * TT;

    float*   s_rec  = (float*)smem_raw;              // [TT][REC] 112KB
    float*   s_aext = s_rec + TT * REC;              // [2][KMAX] 256B
    int*     s_final= (int*)(s_aext + 2 * KMAX);     // 4B
    short*   s_tag  = (short*)(s_final + 1);         // [TT] 2KB
    uint8_t* s_bp   = (uint8_t*)(s_tag + TT);        // [TT][4] 4KB (slow steps)
    uint8_t* s_cnt  = s_bp + TT * 4;                 // [TT] 1KB

    // ---- stage candidate lists into records (parallel) ----
    for (int t = tid; t < len; t += 256) {
        size_t r = rowbase + t;
        int c = g_cnt[r];
        s_cnt[t] = (uint8_t)c;
        uint32_t i4 = *(const uint32_t*)&g_cidx[r * KMAX];
        float4   p4 = *(const float4*)&g_cpot[r * KMAX];
        float* rp = s_rec + t * REC;
        *(float4*)(rp + 16) = p4;
        ((uint32_t*)rp)[20] = i4;
        ((uint32_t*)rp)[21] = (uint32_t)c;           // flag clear (slow default)
    }
    __syncthreads();

    // ---- gather 4x4 trans blocks for fast steps; set fast flag (parallel) ----
    for (int t = tid + 1; t < len; t += 256) {
        int cp_ = s_cnt[t - 1], cc_ = s_cnt[t];
        if (cp_ <= KF && cc_ <= KF) {
            uint32_t ip = ((const uint32_t*)(s_rec + (t - 1) * REC))[20];
            float* rp = s_rec + t * REC;
            uint32_t ic = ((const uint32_t*)rp)[20];
            #pragma unroll
            for (int pi = 0; pi < 4; pi++) {
                float4 v = make_float4(0.f, 0.f, 0.f, 0.f);
                if (pi < cp_) {
                    const float* trow = trans + (int)((ip >> (pi * 8)) & 0xffu) * NN;
                    v.x = __ldg(&trow[ic & 0xffu]);
                    if (cc_ > 1) v.y = __ldg(&trow[(ic >> 8)  & 0xffu]);
                    if (cc_ > 2) v.z = __ldg(&trow[(ic >> 16) & 0xffu]);
                    if (cc_ > 3) v.w = __ldg(&trow[(ic >> 24) & 0xffu]);
                }
                *(float4*)(rp + pi * 4) = v;
            }
            ((uint32_t*)rp)[21] = (uint32_t)cc_ | 0x80u;
        }
    }
    __syncthreads();

    // ---- recurrence (warp 0; all lanes replicated, zero shuffles) ----
    if (tid < 32) {
        const int lane = tid;
        const bool l0 = (lane == 0);

        int cp0 = s_cnt[0];
        float4 p0 = *(const float4*)(s_rec + 16);
        float a0 = p0.x;
        float a1 = (cp0 > 1) ? p0.y : NEGF;
        float a2 = (cp0 > 2) ? p0.z : NEGF;
        float a3 = (cp0 > 3) ? p0.w : NEGF;
        uint32_t idxp = ((const uint32_t*)s_rec)[20];
        if (l0) *(float4*)(s_rec + 24) = make_float4(a0, a1, a2, a3); // row 0 alphas
        int curext = 0;
        if (cp0 > KF) {
            if (lane < cp0) s_aext[lane] = g_cpot[rowbase * KMAX + lane];
        }
        __syncwarp();

        // one-step-ahead operand buffer
        float4 q0N = {0,0,0,0}, q1N = {0,0,0,0}, q2N = {0,0,0,0},
               q3N = {0,0,0,0}, ptN = {0,0,0,0};
        uint32_t ixN = 0, cfN = 0;
        if (len > 1) {
            const float* rp = s_rec + REC;
            q0N = *(const float4*)(rp);      q1N = *(const float4*)(rp + 4);
            q2N = *(const float4*)(rp + 8);  q3N = *(const float4*)(rp + 12);
            ptN = *(const float4*)(rp + 16);
            ixN = ((const uint32_t*)rp)[20]; cfN = ((const uint32_t*)rp)[21];
        }

        for (int t = 1; t < len; t++) {
            float4 r0 = q0N, r1 = q1N, r2 = q2N, r3 = q3N, pt = ptN;
            uint32_t ix = ixN, cf = cfN;
            {   // clamped prefetch of t+1
                int tn = (t + 1 < len) ? (t + 1) : (len - 1);
                const float* rp = s_rec + tn * REC;
                q0N = *(const float4*)(rp);      q1N = *(const float4*)(rp + 4);
                q2N = *(const float4*)(rp + 8);  q3N = *(const float4*)(rp + 12);
                ptN = *(const float4*)(rp + 16);
                ixN = ((const uint32_t*)rp)[20]; cfN = ((const uint32_t*)rp)[21];
            }
            int cc = (int)(cf & 63u);
            float* rpt = s_rec + t * REC;

            if (cf & 0x80u) {
                // ---- fast: value-only 4x4 max-plus (no index tracking) ----
                float m0 = fmaxf(fmaxf(a0 + r0.x, a1 + r1.x),
                                 fmaxf(a2 + r2.x, a3 + r3.x));
                float m1 = fmaxf(fmaxf(a0 + r0.y, a1 + r1.y),
                                 fmaxf(a2 + r2.y, a3 + r3.y));
                float m2 = fmaxf(fmaxf(a0 + r0.z, a1 + r1.z),
                                 fmaxf(a2 + r2.z, a3 + r3.z));
                float m3 = fmaxf(fmaxf(a0 + r0.w, a1 + r1.w),
                                 fmaxf(a2 + r2.w, a3 + r3.w));
                a0 = m0 + pt.x;
                a1 = (cc > 1) ? (m1 + pt.y) : NEGF;
                a2 = (cc > 2) ? (m2 + pt.z) : NEGF;
                a3 = (cc > 3) ? (m3 + pt.w) : NEGF;
                if (l0) *(float4*)(rpt + 24) = make_float4(a0, a1, a2, a3);
            } else {
                // ---- slow: cnt>4 on either side; lane-parallel, stored bp ----
                int cp_ = s_cnt[t - 1];
                float pj = 0.f; int myidx = 0;
                if (lane < cc) {
                    if (lane < KF) { pj = rpt[16 + lane];
                                     myidx = (int)((ix >> (lane * 8)) & 0xffu); }
                    else           { pj = g_cpot[(rowbase + t) * KMAX + lane];
                                     myidx = g_cidx[(rowbase + t) * KMAX + lane]; }
                }
                float bsv = NEGF; int bii = 0;
                for (int i = 0; i < cp_; i++) {
                    float ai = (cp_ <= KF)
                        ? ((i == 0) ? a0 : (i == 1) ? a1 : (i == 2) ? a2 : a3)
                        : s_aext[curext * KMAX + i];
                    int ii = (i < KF) ? (int)((idxp >> (i * 8)) & 0xffu)
                                      : (int)g_cidx[(rowbase + t - 1) * KMAX + i];
                    float tr = (lane < cc) ? __ldg(&trans[ii * NN + myidx]) : 0.f;
                    float v = ai + tr;
                    if (v > bsv) { bsv = v; bii = ii; }   // ascending i = first-max
                }
                if (lane < cc) {
                    s_aext[(curext ^ 1) * KMAX + lane] = bsv + pj;
                    if (lane < KF) s_bp[t * 4 + lane] = (uint8_t)bii;
                    else g_bpo[(rowbase + t) * KMAX + lane] = (uint8_t)bii;
                }
                __syncwarp();
                curext ^= 1;
                a0 = s_aext[curext * KMAX + 0];
                a1 = (cc > 1) ? s_aext[curext * KMAX + 1] : NEGF;
                a2 = (cc > 2) ? s_aext[curext * KMAX + 2] : NEGF;
                a3 = (cc > 3) ? s_aext[curext * KMAX + 3] : NEGF;
                if (l0) *(float4*)(rpt + 24) = make_float4(a0, a1, a2, a3);
                __syncwarp();
            }
            idxp = ix;
        }

        // ---- final argmax over last row's candidates ----
        int cpL = s_cnt[len - 1];
        int btag;
        if (cpL <= KF) {
            float bv = a0; int bs = 0;
            if (a1 > bv) { bv = a1; bs = 1; }
            if (a2 > bv) { bv = a2; bs = 2; }
            if (a3 > bv) { bv = a3; bs = 3; }
            btag = (int)((idxp >> (bs * 8)) & 0xffu);
        } else {
            float bv = NEGF; btag = 0;
            for (int p = 0; p < cpL; p++) {
                float v = s_aext[curext * KMAX + p];
                if (v > bv) {
                    bv = v;
                    btag = (p < KF) ? (int)((idxp >> (p * 8)) & 0xffu)
                                    : (int)g_cidx[(rowbase + len - 1) * KMAX + p];
                }
            }
        }
        if (l0) *s_final = btag;
    }
    __syncthreads();

    // ---- parallel anchor backtrack (singleton rows force the path) ----
    // Fast steps: recompute bp from stored alphas (identical fadds + ascending
    // strict-> == reference first-argmax). Slow steps: stored bp.
    for (int r = tid; r < len; r += 256) {
        bool anchor = (s_cnt[r] == 1) || (r == len - 1);
        if (!anchor) continue;
        int tag = (r == len - 1) ? *s_final
                                 : (int)(((const uint32_t*)(s_rec + r * REC))[20] & 0xffu);
        s_tag[r] = (short)tag;
        int t = r;
        while (t >= 1 && s_cnt[t - 1] != 1) {
            const float* rpt = s_rec + t * REC;
            uint32_t cf = ((const uint32_t*)rpt)[21];
            uint32_t ic = ((const uint32_t*)rpt)[20];
            int cc = (int)(cf & 63u);
            int prev;
            if (cf & 0x80u) {
                int pj = 0;   // find tag's slot (cc <= 4)
                while ((int)((ic >> (pj * 8)) & 0xffu) != tag) pj++;
                const float* rpp = s_rec + (t - 1) * REC;
                float A0 = rpp[24], A1 = rpp[25], A2 = rpp[26], A3 = rpp[27];
                float bv = A0 + rpt[pj];      int bpi = 0;
                float v  = A1 + rpt[4 + pj];  if (v > bv) { bv = v; bpi = 1; }
                v        = A2 + rpt[8 + pj];  if (v > bv) { bv = v; bpi = 2; }
                v        = A3 + rpt[12 + pj]; if (v > bv) { bv = v; bpi = 3; }
                prev = (int)((((const uint32_t*)rpp)[20] >> (bpi * 8)) & 0xffu);
            } else {
                int pj = 0;
                if (cc > 1) {
                    for (;;) {
                        int j = (pj < KF) ? (int)((ic >> (pj * 8)) & 0xffu)
                                          : (int)g_cidx[(rowbase + t) * KMAX + pj];
                        if (j == tag) break;
                        pj++;
                    }
                }
                prev = (pj < KF) ? (int)s_bp[t * 4 + pj]
                                 : (int)g_bpo[(rowbase + t) * KMAX + pj];
            }
            tag = prev;
            t--;
            s_tag[t] = (short)tag;
        }
    }
    __syncthreads();

    // ---- fused one-hot write: this batch's 1MB, float4 stores ----
    float4* outb = (float4*)(out + (size_t)b * TT * NN);
    for (int k = tid; k < TT * (NN / 4); k += 256) {
        int t  = k >> 6;
        int j0 = (k & 63) << 2;
        int tg = (t < len) ? (int)s_tag[t] : 0;
        float4 v;
        v.x = (j0     == tg) ? 1.f : 0.f;
        v.y = (j0 + 1 == tg) ? 1.f : 0.f;
        v.z = (j0 + 2 == tg) ? 1.f : 0.f;
        v.w = (j0 + 3 == tg) ? 1.f : 0.f;
        outb[k] = v;
    }
}

extern "C" void kernel_launch(void* const* d_in, const int* in_sizes, int n_in,
                              void* d_out, int out_size)
{
    const float* pot   = (const float*)d_in[0];   // [B, T, N] fp32
    const float* trans = (const float*)d_in[1];   // [N, N]   fp32
    const int*   lens  = (const int*)d_in[2];     // [B]      int32
    float*       out   = (float*)d_out;           // [B, T, N] fp32 one-hot

    const int SMEM_BYTES = TT * REC * 4 + 2 * KMAX * 4 + 4
                         + TT * 2 + TT * 4 + TT;   // 122116B
    cudaFuncSetAttribute(walk_kernel, cudaFuncAttributeMaxDynamicSharedMemorySize,
                         SMEM_BYTES);

    cand_kernel<<<(BB * TT) / 8, 256>>>(pot);
    walk_kernel<<<BB, 256, SMEM_BYTES>>>(trans, lens, out);
}

// round 9
// speedup vs baseline: 3.9019x; 1.2596x over previous
#include <cuda_runtime.h>
#include <stdint.h>

#define BB 128
#define TT 1024
#define NN 256
#define FULL 0xffffffffu
#define KMAX 32      // hard cap on candidates (global storage)
#define KF   4       // fast-path candidate cap
#define REC  28      // floats per record (112B): [0:16) trans4x4, [16:20) pot
                     // (NEGF-masked), [20] idx u8x4, [21] cnt|0x80, [24:28) alphas
#define NEGF (-3.4e38f)

// Scratch (device globals; allocation-free per harness rules)
__device__ uint8_t g_cnt [BB * TT];
__device__ uint8_t g_cidx[(size_t)BB * TT * KMAX];
__device__ float   g_cpot[(size_t)BB * TT * KMAX];
__device__ uint8_t g_bpo [(size_t)BB * TT * KMAX];   // slow-step bp, slot >= KF

__device__ __forceinline__ unsigned fkey(float x) {
    unsigned b = __float_as_uint(x);
    return b ^ ((unsigned)((int)b >> 31) | 0x80000000u);
}
__device__ __forceinline__ float finv(unsigned u) {
    return __uint_as_float(u ^ (~(unsigned)((int)u >> 31) | 0x80000000u));
}

// ---------------------------------------------------------------------------
// Phase 1: candidate extraction (66% of HBM roofline).
// All possible argmax sources / ties / winners at row t lie in
// C_t = { i : pot_t[i] >= max(pot_t) - 0.22 }   (transitions span ±0.05).
// Candidates emitted ascending by state index.
// ---------------------------------------------------------------------------
__global__ __launch_bounds__(256) void cand_kernel(const float* __restrict__ pot)
{
    int row  = (blockIdx.x << 3) + (threadIdx.x >> 5);
    int lane = threadIdx.x & 31;
    const float* r = pot + (size_t)row * NN;

    float a[8];
    #pragma unroll
    for (int k = 0; k < 8; k++) a[k] = __ldcs(&r[(k << 5) + lane]);

    float m = fmaxf(fmaxf(fmaxf(a[0], a[1]), fmaxf(a[2], a[3])),
                    fmaxf(fmaxf(a[4], a[5]), fmaxf(a[6], a[7])));
    m = finv(__reduce_max_sync(FULL, fkey(m)));
    float thr = m - 0.22f;

    int base = 0;
    #pragma unroll
    for (int k = 0; k < 8; k++) {
        unsigned mm = __ballot_sync(FULL, a[k] >= thr);
        if (a[k] >= thr) {
            int pos = base + __popc(mm & ((1u << lane) - 1u));
            if (pos < KMAX) {
                g_cidx[(size_t)row * KMAX + pos] = (uint8_t)((k << 5) + lane);
                g_cpot[(size_t)row * KMAX + pos] = a[k];
            }
        }
        base += __popc(mm);
    }
    if (lane == 0) g_cnt[row] = (uint8_t)min(base, KMAX);
}

// step macro: value-only 4x4 max-plus (pot pre-masked => no SELs, no cc)
#define VSTEP(C0, C1, C2, C3, CPT, RP)                                   \
    {                                                                     \
        float m0 = fmaxf(fmaxf(a0 + (C0).x, a1 + (C1).x),                \
                         fmaxf(a2 + (C2).x, a3 + (C3).x));               \
        float m1 = fmaxf(fmaxf(a0 + (C0).y, a1 + (C1).y),                \
                         fmaxf(a2 + (C2).y, a3 + (C3).y));               \
        float m2 = fmaxf(fmaxf(a0 + (C0).z, a1 + (C1).z),                \
                         fmaxf(a2 + (C2).z, a3 + (C3).z));               \
        float m3 = fmaxf(fmaxf(a0 + (C0).w, a1 + (C1).w),                \
                         fmaxf(a2 + (C2).w, a3 + (C3).w));               \
        a0 = m0 + (CPT).x; a1 = m1 + (CPT).y;                            \
        a2 = m2 + (CPT).z; a3 = m3 + (CPT).w;                            \
        if (l0) *(float4*)((RP) + 24) = make_float4(a0, a1, a2, a3);     \
    }

// ---------------------------------------------------------------------------
// Phase 2: walk + backtrack + fused one-hot write. One block per batch.
// Chain = branchless value-only segments between slow (cnt>4) steps.
// ---------------------------------------------------------------------------
extern __shared__ char smem_raw[];

__global__ __launch_bounds__(256) void walk_kernel(const float* __restrict__ trans,
                                                   const int*   __restrict__ lens,
                                                   float*       __restrict__ out)
{
    const int b   = blockIdx.x;
    const int tid = threadIdx.x;
    const int len = lens[b];
    const size_t rowbase = (size_t)b * TT;

    float*   s_rec  = (float*)smem_raw;              // [TT][REC] 112KB
    float*   s_aext = s_rec + TT * REC;              // [2][KMAX] 256B
    int*     s_final= (int*)(s_aext + 2 * KMAX);     // 4B
    short*   s_tag  = (short*)(s_final + 1);         // [TT] 2KB
    short*   s_slow = s_tag + TT;                    // [TT] 2KB (uncapped list)
    uint8_t* s_bp   = (uint8_t*)(s_slow + TT);       // [TT][4] 4KB (slow steps)
    uint8_t* s_cnt  = s_bp + TT * 4;                 // [TT] 1KB

    // ---- stage candidate lists into records; pre-mask pot with NEGF ----
    for (int t = tid; t < len; t += 256) {
        size_t r = rowbase + t;
        int c = g_cnt[r];
        s_cnt[t] = (uint8_t)c;
        uint32_t i4 = *(const uint32_t*)&g_cidx[r * KMAX];
        float4   p4 = *(const float4*)&g_cpot[r * KMAX];
        if (c < 2) p4.y = NEGF;
        if (c < 3) p4.z = NEGF;
        if (c < 4) p4.w = NEGF;
        float* rp = s_rec + t * REC;
        *(float4*)(rp + 16) = p4;
        ((uint32_t*)rp)[20] = i4;
        ((uint32_t*)rp)[21] = (uint32_t)c;           // flag clear (slow default)
    }
    __syncthreads();

    // ---- gather 4x4 trans blocks for fast steps; set fast flag ----
    for (int t = tid + 1; t < len; t += 256) {
        int cp_ = s_cnt[t - 1], cc_ = s_cnt[t];
        if (cp_ <= KF && cc_ <= KF) {
            uint32_t ip = ((const uint32_t*)(s_rec + (t - 1) * REC))[20];
            float* rp = s_rec + t * REC;
            uint32_t ic = ((const uint32_t*)rp)[20];
            #pragma unroll
            for (int pi = 0; pi < 4; pi++) {
                float4 v = make_float4(0.f, 0.f, 0.f, 0.f);
                if (pi < cp_) {
                    const float* trow = trans + (int)((ip >> (pi * 8)) & 0xffu) * NN;
                    v.x = __ldg(&trow[ic & 0xffu]);
                    if (cc_ > 1) v.y = __ldg(&trow[(ic >> 8)  & 0xffu]);
                    if (cc_ > 2) v.z = __ldg(&trow[(ic >> 16) & 0xffu]);
                    if (cc_ > 3) v.w = __ldg(&trow[(ic >> 24) & 0xffu]);
                }
                *(float4*)(rp + pi * 4) = v;
            }
            ((uint32_t*)rp)[21] = (uint32_t)cc_ | 0x80u;
        }
    }
    __syncthreads();

    // ---- recurrence (warp 0; all lanes replicated, zero shuffles) ----
    if (tid < 32) {
        const int lane = tid;
        const bool l0 = (lane == 0);

        // build ordered slow-step list via ballot compaction (uncapped)
        int nslow = 0;
        for (int base = 0; base < len; base += 32) {
            int t = base + lane;
            bool slow = (t >= 1) && (t < len) &&
                        !(((const uint32_t*)(s_rec + t * REC))[21] & 0x80u);
            unsigned mb = __ballot_sync(FULL, slow);
            if (slow)
                s_slow[nslow + __popc(mb & ((1u << lane) - 1u))] = (short)t;
            nslow += __popc(mb);
        }

        int cp0 = s_cnt[0];
        float4 p0 = *(const float4*)(s_rec + 16);    // masked pot row 0
        float a0 = p0.x, a1 = p0.y, a2 = p0.z, a3 = p0.w;
        uint32_t idxp = ((const uint32_t*)s_rec)[20];
        if (l0) *(float4*)(s_rec + 24) = make_float4(a0, a1, a2, a3);
        int curext = 0;
        if (cp0 > KF) {
            if (lane < cp0) s_aext[lane] = g_cpot[rowbase * KMAX + lane];
        }
        __syncwarp();

        int t = 1, si = 0;
        while (t < len) {
            int tend = (si < nslow) ? (int)s_slow[si] : len;
            if (t < tend) {
                // ---- branchless pipelined segment [t, tend) ----
                float* rp = s_rec + t * REC;
                float4 c0 = *(const float4*)(rp);
                float4 c1 = *(const float4*)(rp + 4);
                float4 c2 = *(const float4*)(rp + 8);
                float4 c3 = *(const float4*)(rp + 12);
                float4 cp = *(const float4*)(rp + 16);
                for (int u = t; u < tend - 1; u++) {
                    float* rn = rp + REC;
                    float4 n0 = *(const float4*)(rn);
                    float4 n1 = *(const float4*)(rn + 4);
                    float4 n2 = *(const float4*)(rn + 8);
                    float4 n3 = *(const float4*)(rn + 12);
                    float4 np = *(const float4*)(rn + 16);
                    VSTEP(c0, c1, c2, c3, cp, rp)
                    c0 = n0; c1 = n1; c2 = n2; c3 = n3; cp = np;
                    rp = rn;
                }
                VSTEP(c0, c1, c2, c3, cp, rp)       // peeled last step
                idxp = ((const uint32_t*)(s_rec + (tend - 1) * REC))[20];
                t = tend;
            }
            if (t >= len) break;
            // ---- slow step at t (cnt>4 on either side; lane-parallel) ----
            {
                float* rpt = s_rec + t * REC;
                int cc  = s_cnt[t];
                int cp_ = s_cnt[t - 1];
                uint32_t ix = ((const uint32_t*)rpt)[20];
                float pj = 0.f; int myidx = 0;
                if (lane < cc) {
                    if (lane < KF) { pj = rpt[16 + lane];
                                     myidx = (int)((ix >> (lane * 8)) & 0xffu); }
                    else           { pj = g_cpot[(rowbase + t) * KMAX + lane];
                                     myidx = g_cidx[(rowbase + t) * KMAX + lane]; }
                }
                float bsv = NEGF; int bii = 0;
                for (int i = 0; i < cp_; i++) {
                    float ai = (cp_ <= KF)
                        ? ((i == 0) ? a0 : (i == 1) ? a1 : (i == 2) ? a2 : a3)
                        : s_aext[curext * KMAX + i];
                    int ii = (i < KF) ? (int)((idxp >> (i * 8)) & 0xffu)
                                      : (int)g_cidx[(rowbase + t - 1) * KMAX + i];
                    float tr = (lane < cc) ? __ldg(&trans[ii * NN + myidx]) : 0.f;
                    float v = ai + tr;
                    if (v > bsv) { bsv = v; bii = ii; }   // ascending i = first-max
                }
                if (lane < cc) {
                    s_aext[(curext ^ 1) * KMAX + lane] = bsv + pj;
                    if (lane < KF) s_bp[t * 4 + lane] = (uint8_t)bii;
                    else g_bpo[(rowbase + t) * KMAX + lane] = (uint8_t)bii;
                }
                __syncwarp();
                curext ^= 1;
                a0 = s_aext[curext * KMAX + 0];
                a1 = (cc > 1) ? s_aext[curext * KMAX + 1] : NEGF;
                a2 = (cc > 2) ? s_aext[curext * KMAX + 2] : NEGF;
                a3 = (cc > 3) ? s_aext[curext * KMAX + 3] : NEGF;
                if (l0) *(float4*)(rpt + 24) = make_float4(a0, a1, a2, a3);
                __syncwarp();
                idxp = ((const uint32_t*)rpt)[20];
                t++; si++;
            }
        }

        // ---- final argmax over last row's candidates ----
        int cpL = s_cnt[len - 1];
        int btag;
        if (cpL <= KF) {
            float bv = a0; int bs = 0;
            if (a1 > bv) { bv = a1; bs = 1; }
            if (a2 > bv) { bv = a2; bs = 2; }
            if (a3 > bv) { bv = a3; bs = 3; }
            btag = (int)((idxp >> (bs * 8)) & 0xffu);
        } else {
            float bv = NEGF; btag = 0;
            for (int p = 0; p < cpL; p++) {
                float v = s_aext[curext * KMAX + p];
                if (v > bv) {
                    bv = v;
                    btag = (p < KF) ? (int)((idxp >> (p * 8)) & 0xffu)
                                    : (int)g_cidx[(rowbase + len - 1) * KMAX + p];
                }
            }
        }
        if (l0) *s_final = btag;
    }
    __syncthreads();

    // ---- parallel anchor backtrack (singleton rows force the path) ----
    // Fast steps: recompute bp from stored alphas (identical fadds + ascending
    // strict-> == reference first-argmax). Slow steps: stored bp.
    for (int r = tid; r < len; r += 256) {
        bool anchor = (s_cnt[r] == 1) || (r == len - 1);
        if (!anchor) continue;
        int tag = (r == len - 1) ? *s_final
                                 : (int)(((const uint32_t*)(s_rec + r * REC))[20] & 0xffu);
        s_tag[r] = (short)tag;
        int t = r;
        while (t >= 1 && s_cnt[t - 1] != 1) {
            const float* rpt = s_rec + t * REC;
            uint32_t cf = ((const uint32_t*)rpt)[21];
            uint32_t ic = ((const uint32_t*)rpt)[20];
            int cc = (int)(cf & 63u);
            int prev;
            if (cf & 0x80u) {
                int pj = 0;   // find tag's slot (cc <= 4)
                while ((int)((ic >> (pj * 8)) & 0xffu) != tag) pj++;
                const float* rpp = s_rec + (t - 1) * REC;
                float A0 = rpp[24], A1 = rpp[25], A2 = rpp[26], A3 = rpp[27];
                float bv = A0 + rpt[pj];      int bpi = 0;
                float v  = A1 + rpt[4 + pj];  if (v > bv) { bv = v; bpi = 1; }
                v        = A2 + rpt[8 + pj];  if (v > bv) { bv = v; bpi = 2; }
                v        = A3 + rpt[12 + pj]; if (v > bv) { bv = v; bpi = 3; }
                prev = (int)((((const uint32_t*)rpp)[20] >> (bpi * 8)) & 0xffu);
            } else {
                int pj = 0;
                if (cc > 1) {
                    for (;;) {
                        int j = (pj < KF) ? (int)((ic >> (pj * 8)) & 0xffu)
                                          : (int)g_cidx[(rowbase + t) * KMAX + pj];
                        if (j == tag) break;
                        pj++;
                    }
                }
                prev = (pj < KF) ? (int)s_bp[t * 4 + pj]
                                 : (int)g_bpo[(rowbase + t) * KMAX + pj];
            }
            tag = prev;
            t--;
            s_tag[t] = (short)tag;
        }
    }
    __syncthreads();

    // ---- fused one-hot write: this batch's 1MB, float4 stores ----
    float4* outb = (float4*)(out + (size_t)b * TT * NN);
    for (int k = tid; k < TT * (NN / 4); k += 256) {
        int t  = k >> 6;
        int j0 = (k & 63) << 2;
        int tg = (t < len) ? (int)s_tag[t] : 0;
        float4 v;
        v.x = (j0     == tg) ? 1.f : 0.f;
        v.y = (j0 + 1 == tg) ? 1.f : 0.f;
        v.z = (j0 + 2 == tg) ? 1.f : 0.f;
        v.w = (j0 + 3 == tg) ? 1.f : 0.f;
        outb[k] = v;
    }
}

extern "C" void kernel_launch(void* const* d_in, const int* in_sizes, int n_in,
                              void* d_out, int out_size)
{
    const float* pot   = (const float*)d_in[0];   // [B, T, N] fp32
    const float* trans = (const float*)d_in[1];   // [N, N]   fp32
    const int*   lens  = (const int*)d_in[2];     // [B]      int32
    float*       out   = (float*)d_out;           // [B, T, N] fp32 one-hot

    const int SMEM_BYTES = TT * REC * 4 + 2 * KMAX * 4 + 4
                         + TT * 2 + TT * 2 + TT * 4 + TT;   // ~124KB
    cudaFuncSetAttribute(walk_kernel, cudaFuncAttributeMaxDynamicSharedMemorySize,
                         SMEM_BYTES);

    cand_kernel<<<(BB * TT) / 8, 256>>>(pot);
    walk_kernel<<<BB, 256, SMEM_BYTES>>>(trans, lens, out);
}